// round 4
// baseline (speedup 1.0000x reference)
#include <cuda_runtime.h>
#include <cuda_bf16.h>
#include <cstdint>

// SGC degree-2: out = A @ (A @ x)
// x: [N=100000, D=64] fp32, E = 3.2M edges
// edge_index: [2, E] = [dst; src]. NOTE: JAX x64 is disabled by default, so
// .astype(jnp.int64) in the reference silently yields INT32. Reading it as
// int64 reinterprets two packed ids as one huge index -> the illegal access
// seen in R2/R3. Read as int32.
//
// Scatter SpMM with vector reductions:
//  - 16 threads per edge, each owns a float4 (16B) chunk of the 64-float row.
//  - red.global.add.v4.f32 -> 1 REDG per 16B instead of 4 scalar atomicAdds.
//  - x (25.6MB) and accumulators (25.6MB) fit in L2 (~126MB).

#define N_NODES 100000
#define D 64
#define THREADS_PER_EDGE 16   // 64 floats / 4 per thread

__device__ __align__(16) float g_tmp[N_NODES * D];

__global__ void zero_bufs(float* __restrict__ out)
{
    long long i = (long long)blockIdx.x * blockDim.x + threadIdx.x;
    const long long n = (long long)N_NODES * D;
    if (i < n) {
        g_tmp[i] = 0.0f;
        out[i]   = 0.0f;
    }
}

// PASS=0: read x from arg, write g_tmp. PASS=1: read g_tmp, write arg out.
template <int PASS>
__global__ void spmm_scatter_v4(const int* __restrict__ dst,
                                const int* __restrict__ src,
                                const float* __restrict__ w,
                                const float* __restrict__ xio,
                                int E)
{
    long long gid = (long long)blockIdx.x * blockDim.x + threadIdx.x;
    int e = (int)(gid >> 4);          // edge id
    int c = ((int)gid & 15) << 2;     // feature offset (floats), 16B aligned
    if (e >= E) return;

    int s = src[e];                   // broadcast within the 16-thread group
    int d = dst[e];
    float wv = w[e];

    const float* xin = (PASS == 0) ? xio : g_tmp;
    float*       acc = (PASS == 0) ? g_tmp : const_cast<float*>(xio);

    const float4 v = *reinterpret_cast<const float4*>(xin + (long long)s * D + c);
    float a0 = v.x * wv;
    float a1 = v.y * wv;
    float a2 = v.z * wv;
    float a3 = v.w * wv;

    float* p = acc + (long long)d * D + c;
    asm volatile("red.global.add.v4.f32 [%0], {%1, %2, %3, %4};"
                 :: "l"(p), "f"(a0), "f"(a1), "f"(a2), "f"(a3)
                 : "memory");
}

extern "C" void kernel_launch(void* const* d_in, const int* in_sizes, int n_in,
                              void* d_out, int out_size)
{
    const float* features    = (const float*)d_in[0];   // [N, 64]
    const float* edge_weight = (const float*)d_in[1];   // [E]
    const int*   edge_index  = (const int*)d_in[2];     // [2, E] int32: dst row, src row
    // d_in[3] = degree (always 2 per setup_inputs; cannot sync-read during capture)

    int E = in_sizes[1];
    const int* dst  = edge_index;
    const int* srcp = edge_index + E;

    float* out = (float*)d_out;

    // zero accumulators (d_out is poisoned 0xAA by the harness)
    {
        long long n = (long long)N_NODES * D;
        int t = 256;
        int b = (int)((n + t - 1) / t);
        zero_bufs<<<b, t>>>(out);
    }

    long long total = (long long)E * THREADS_PER_EDGE;
    int threads = 256;
    int blocks = (int)((total + threads - 1) / threads);

    // pass 1: g_tmp = A @ features
    spmm_scatter_v4<0><<<blocks, threads>>>(dst, srcp, edge_weight, features, E);
    // pass 2: out = A @ g_tmp
    spmm_scatter_v4<1><<<blocks, threads>>>(dst, srcp, edge_weight, out, E);
}

// round 5
// speedup vs baseline: 1.0539x; 1.0539x over previous
#include <cuda_runtime.h>
#include <cuda_bf16.h>
#include <cstdint>

// SGC degree-2: out = A @ (A @ x)
// x: [N=100000, D=64] fp32, E = 3.2M, edge_index int32 [2,E] = [dst; src]
//
// R5: replace atomic-scatter SpMM (L2-roofline-bound at 362us) with
// build-CSR-once + gather-form SpMM:
//   1. histogram of dst            (atomicAdd int)
//   2. exclusive scan (single CTA) -> row_ptr, row cursor
//   3. fill packed {src, w} per row slot
//   4. 2x gather SpMM: warp-per-row, register accumulate, plain stores.
// Scatter traffic per pass drops 819MB -> 26MB; no output pre-zeroing needed.

#define N_NODES 100000
#define D 64
#define E_MAX 3200000
#define SCAN_T 1024

__device__ __align__(16) float g_tmp[N_NODES * D];
__device__ __align__(16) int2  g_edges[E_MAX];   // {src, w as int bits}
__device__ int g_cnt[N_NODES];
__device__ int g_ptr[N_NODES + 1];
__device__ int g_cur[N_NODES];

__global__ void zero_cnt()
{
    int i = blockIdx.x * blockDim.x + threadIdx.x;
    if (i < N_NODES) g_cnt[i] = 0;
}

__global__ void hist(const int* __restrict__ dst, int E)
{
    int e = blockIdx.x * blockDim.x + threadIdx.x;
    if (e < E) atomicAdd(&g_cnt[dst[e]], 1);
}

// Single-CTA exclusive scan over N_NODES counts -> g_ptr (+ cursor copy).
__global__ void scan_kernel(int E)
{
    __shared__ int s[SCAN_T];
    int tid = threadIdx.x;
    const int chunk = (N_NODES + SCAN_T - 1) / SCAN_T;
    int start = tid * chunk;
    int end   = start + chunk;
    if (end > N_NODES) end = N_NODES;
    if (start > N_NODES) start = N_NODES;

    int sum = 0;
    for (int i = start; i < end; i++) sum += g_cnt[i];
    s[tid] = sum;
    __syncthreads();

    // inclusive Hillis-Steele scan over SCAN_T partials
    for (int off = 1; off < SCAN_T; off <<= 1) {
        int v = 0;
        if (tid >= off) v = s[tid - off];
        __syncthreads();
        s[tid] += v;
        __syncthreads();
    }

    int run = s[tid] - sum;   // exclusive offset of this thread's chunk
    for (int i = start; i < end; i++) {
        g_ptr[i] = run;
        g_cur[i] = run;
        run += g_cnt[i];
    }
    if (tid == SCAN_T - 1) g_ptr[N_NODES] = s[SCAN_T - 1];  // == E
}

__global__ void fill(const int* __restrict__ dst,
                     const int* __restrict__ src,
                     const float* __restrict__ w, int E)
{
    int e = blockIdx.x * blockDim.x + threadIdx.x;
    if (e < E) {
        int slot = atomicAdd(&g_cur[dst[e]], 1);
        g_edges[slot] = make_int2(src[e], __float_as_int(w[e]));
    }
}

// Gather SpMM: 1 warp per dst row, each lane owns 2 consecutive floats.
// PASS=0: xarg -> g_tmp.  PASS=1: g_tmp -> outarg.
template <int PASS>
__global__ void spmm_gather(const float* __restrict__ xarg,
                            float* __restrict__ outarg)
{
    int row  = blockIdx.x * (blockDim.x >> 5) + (threadIdx.x >> 5);
    if (row >= N_NODES) return;
    int lane = threadIdx.x & 31;

    const float* __restrict__ xin = (PASS == 0) ? xarg : g_tmp;
    float* __restrict__ outp      = (PASS == 0) ? g_tmp : outarg;

    int beg = g_ptr[row];
    int end = g_ptr[row + 1];

    float a0 = 0.0f, a1 = 0.0f;
    int c = lane * 2;

    int i = beg;
    for (; i + 4 <= end; i += 4) {
        // 4 independent meta loads (broadcast), then 4 independent row loads
        int2 e0 = g_edges[i + 0];
        int2 e1 = g_edges[i + 1];
        int2 e2 = g_edges[i + 2];
        int2 e3 = g_edges[i + 3];
        float2 v0 = *reinterpret_cast<const float2*>(xin + (long long)e0.x * D + c);
        float2 v1 = *reinterpret_cast<const float2*>(xin + (long long)e1.x * D + c);
        float2 v2 = *reinterpret_cast<const float2*>(xin + (long long)e2.x * D + c);
        float2 v3 = *reinterpret_cast<const float2*>(xin + (long long)e3.x * D + c);
        float w0 = __int_as_float(e0.y);
        float w1 = __int_as_float(e1.y);
        float w2 = __int_as_float(e2.y);
        float w3 = __int_as_float(e3.y);
        a0 += w0 * v0.x; a1 += w0 * v0.y;
        a0 += w1 * v1.x; a1 += w1 * v1.y;
        a0 += w2 * v2.x; a1 += w2 * v2.y;
        a0 += w3 * v3.x; a1 += w3 * v3.y;
    }
    for (; i < end; i++) {
        int2 e = g_edges[i];
        float2 v = *reinterpret_cast<const float2*>(xin + (long long)e.x * D + c);
        float wv = __int_as_float(e.y);
        a0 += wv * v.x; a1 += wv * v.y;
    }

    *reinterpret_cast<float2*>(outp + (long long)row * D + c) = make_float2(a0, a1);
}

extern "C" void kernel_launch(void* const* d_in, const int* in_sizes, int n_in,
                              void* d_out, int out_size)
{
    const float* features    = (const float*)d_in[0];   // [N, 64]
    const float* edge_weight = (const float*)d_in[1];   // [E]
    const int*   edge_index  = (const int*)d_in[2];     // [2, E] int32: dst, src
    // d_in[3] = degree (always 2 per setup_inputs)

    int E = in_sizes[1];
    const int* dst  = edge_index;
    const int* srcp = edge_index + E;
    float* out = (float*)d_out;

    const int T = 256;

    // --- build CSR (once, reused by both passes) ---
    zero_cnt<<<(N_NODES + T - 1) / T, T>>>();
    hist<<<(E + T - 1) / T, T>>>(dst, E);
    scan_kernel<<<1, SCAN_T>>>(E);
    fill<<<(E + T - 1) / T, T>>>(dst, srcp, edge_weight, E);

    // --- 2x gather SpMM (warp per row; 8 rows per 256-thread block) ---
    int rows_per_block = T / 32;
    int blocks = (N_NODES + rows_per_block - 1) / rows_per_block;
    spmm_gather<0><<<blocks, T>>>(features, out);
    spmm_gather<1><<<blocks, T>>>(features, out);
}